// round 1
// baseline (speedup 1.0000x reference)
#include <cuda_runtime.h>

// Shapes (compile-time constants from the reference)
constexpr int B  = 2;
constexpr int L  = 24;
constexpr int R  = 8;
constexpr int C  = 32;
constexpr int H  = 48;
constexpr int WF = 49;

constexpr int RCW  = R * C * WF;        // 12,544   (A elements per (b,l))
constexpr int HW   = H * WF;            // 2,352
constexpr int RCHW = R * C * H * WF;    // 602,112  (u elements per (b,l))
constexpr int NA   = B * L * RCW;       // 602,112  (total A elements)
constexpr int NU   = B * L * RCHW;      // 28,901,376 (total u elements per array)

// Scratch for precomputed transition coefficients A = decay * (cos, sin).
// Interleaved float2 so the main kernel does one 8B load per (element, step).
// 602,112 * 8 B = 4.8 MB -> resident in L2 (126 MB) during the scan kernel.
__device__ float2 g_A[NA];

// ---------------------------------------------------------------------------
// Kernel 1: A[b,l,r,c,w] = exp(-nu*dt) * (cos(th*dt), sin(th*dt))
// 602K elements -> trivial (~few us). Precise expf/sincosf: accuracy headroom,
// cost irrelevant at this size. Avoids 48x redundant MUFU work in the scan.
// ---------------------------------------------------------------------------
__global__ void compute_A_kernel(const float* __restrict__ nu_rate,
                                 const float* __restrict__ theta_rate,
                                 const float* __restrict__ dt_seq) {
    int i = blockIdx.x * blockDim.x + threadIdx.x;
    if (i >= NA) return;
    int bl = i / RCW;                 // 0..B*L-1
    float dt = dt_seq[bl];
    float decay = expf(-nu_rate[i] * dt);
    float s, c;
    sincosf(theta_rate[i] * dt, &s, &c);
    g_A[i] = make_float2(decay * c, decay * s);
}

// ---------------------------------------------------------------------------
// Kernel 2: sequential complex recurrence over L in registers.
// One thread owns 4 consecutive flat channels (float4-vectorized u/out).
// h_l = A_l * h_{l-1} + u_l  (complex), h_{-1} = 0  =>  h_0 = u_0.
// ---------------------------------------------------------------------------
__global__ void __launch_bounds__(256)
scan_kernel(const float4* __restrict__ ur,
            const float4* __restrict__ ui,
            float4* __restrict__ out) {
    int t = blockIdx.x * blockDim.x + threadIdx.x;   // 0 .. 301,055
    int base = t * 4;                                 // global element index
    int b    = base / RCHW;                           // batch
    int flat = base - b * RCHW;                       // channel within batch

    // A index per lane: a_flat = (rc)*WF + w where rc = e/HW, w = e%WF.
    // Constant across l (stride RCW per step), so compute once.
    int aidx0, aidx1, aidx2, aidx3;
    {
        int e0 = flat;
        aidx0 = (e0 / HW) * WF + (e0 % WF);
        int e1 = flat + 1;
        aidx1 = (e1 / HW) * WF + (e1 % WF);
        int e2 = flat + 2;
        aidx2 = (e2 / HW) * WF + (e2 % WF);
        int e3 = flat + 3;
        aidx3 = (e3 / HW) * WF + (e3 % WF);
    }

    float hr0 = 0.f, hi0 = 0.f, hr1 = 0.f, hi1 = 0.f;
    float hr2 = 0.f, hi2 = 0.f, hr3 = 0.f, hi3 = 0.f;

    const int bL = b * L;
    const int flat4 = flat >> 2;

    #pragma unroll
    for (int l = 0; l < L; ++l) {
        const int uoff4 = (bL + l) * (RCHW >> 2) + flat4;  // float4 index
        const float4 vr = ur[uoff4];
        const float4 vi = ui[uoff4];

        const int aoff = (bL + l) * RCW;
        const float2 A0 = g_A[aoff + aidx0];
        const float2 A1 = g_A[aoff + aidx1];
        const float2 A2 = g_A[aoff + aidx2];
        const float2 A3 = g_A[aoff + aidx3];

        float nr, ni;
        nr = A0.x * hr0 - A0.y * hi0 + vr.x;
        ni = A0.x * hi0 + A0.y * hr0 + vi.x;
        hr0 = nr; hi0 = ni;

        nr = A1.x * hr1 - A1.y * hi1 + vr.y;
        ni = A1.x * hi1 + A1.y * hr1 + vi.y;
        hr1 = nr; hi1 = ni;

        nr = A2.x * hr2 - A2.y * hi2 + vr.z;
        ni = A2.x * hi2 + A2.y * hr2 + vi.z;
        hr2 = nr; hi2 = ni;

        nr = A3.x * hr3 - A3.y * hi3 + vr.w;
        ni = A3.x * hi3 + A3.y * hr3 + vi.w;
        hr3 = nr; hi3 = ni;

        out[uoff4]            = make_float4(hr0, hr1, hr2, hr3);  // h_real half
        out[(NU >> 2) + uoff4] = make_float4(hi0, hi1, hi2, hi3); // h_imag half
    }
}

// ---------------------------------------------------------------------------
// kernel_launch: two launches, graph-capturable, no allocations.
// Inputs (metadata order): nu_rate, theta_rate, dt_seq, u_real, u_imag.
// Output: float32, shape (2, B, L, R, C, H, Wf) = 57,802,752 elements.
// ---------------------------------------------------------------------------
extern "C" void kernel_launch(void* const* d_in, const int* in_sizes, int n_in,
                              void* d_out, int out_size) {
    const float*  nu = (const float*)d_in[0];
    const float*  th = (const float*)d_in[1];
    const float*  dt = (const float*)d_in[2];
    const float4* ur = (const float4*)d_in[3];
    const float4* ui = (const float4*)d_in[4];
    float4* out = (float4*)d_out;

    compute_A_kernel<<<(NA + 255) / 256, 256>>>(nu, th, dt);

    constexpr int nthreads = (B * RCHW) / 4;   // 301,056
    scan_kernel<<<nthreads / 256, 256>>>(ur, ui, out);
}

// round 3
// speedup vs baseline: 1.0843x; 1.0843x over previous
#include <cuda_runtime.h>

// Shapes (compile-time constants from the reference)
constexpr int B  = 2;
constexpr int L  = 24;
constexpr int R  = 8;
constexpr int C  = 32;
constexpr int H  = 48;
constexpr int WF = 49;

constexpr int RCW  = R * C * WF;        // 12,544   (A elements per (b,l))
constexpr int HW   = H * WF;            // 2,352
constexpr int RCHW = R * C * H * WF;    // 602,112  (u elements per (b,l))
constexpr int NA   = B * L * RCW;       // 602,112  (total A elements)
constexpr int NU   = B * L * RCHW;      // 28,901,376 (total u elements per array)

// Precomputed transition coefficients A = decay * (cos, sin), interleaved
// float2. 4.8 MB -> L2-resident during the scan kernel.
__device__ float2 g_A[NA];

// ---------------------------------------------------------------------------
// Kernel 1: A[b,l,r,c,w] = exp(-nu*dt) * (cos(th*dt), sin(th*dt))
// ---------------------------------------------------------------------------
__global__ void compute_A_kernel(const float* __restrict__ nu_rate,
                                 const float* __restrict__ theta_rate,
                                 const float* __restrict__ dt_seq) {
    int i = blockIdx.x * blockDim.x + threadIdx.x;
    if (i >= NA) return;
    int bl = i / RCW;                 // 0..B*L-1
    float dt = dt_seq[bl];
    float decay = expf(-nu_rate[i] * dt);
    float s, c;
    sincosf(theta_rate[i] * dt, &s, &c);
    g_A[i] = make_float2(decay * c, decay * s);
}

// ---------------------------------------------------------------------------
// Kernel 2: sequential complex recurrence over L in registers.
// One thread owns 4 consecutive flat channels (float4-vectorized u/out).
// h_l = A_l * h_{l-1} + u_l  (complex), h_{-1} = 0.
//
// __launch_bounds__(256, 4): cap regs at 64 -> 4 CTAs/SM -> 50% occupancy.
// Streaming hints: u is read-once (__ldcs), out is write-only (__stcs) ->
// keep the 4.8 MB A table hot in L2 instead of thrashing it with 462 MB of
// streaming traffic.
// ---------------------------------------------------------------------------
__global__ void __launch_bounds__(256, 4)
scan_kernel(const float4* __restrict__ ur,
            const float4* __restrict__ ui,
            float4* __restrict__ out) {
    int t = blockIdx.x * blockDim.x + threadIdx.x;   // 0 .. 301,055
    int base = t * 4;                                 // global element index
    int b    = base / RCHW;                           // batch
    int flat = base - b * RCHW;                       // channel within batch

    // A index per lane: a_flat = (e/HW)*WF + (e%WF); constant across l
    // (stride RCW per step), so compute once.
    int aidx0, aidx1, aidx2, aidx3;
    {
        int e0 = flat;
        aidx0 = (e0 / HW) * WF + (e0 % WF);
        int e1 = flat + 1;
        aidx1 = (e1 / HW) * WF + (e1 % WF);
        int e2 = flat + 2;
        aidx2 = (e2 / HW) * WF + (e2 % WF);
        int e3 = flat + 3;
        aidx3 = (e3 / HW) * WF + (e3 % WF);
    }

    float hr0 = 0.f, hi0 = 0.f, hr1 = 0.f, hi1 = 0.f;
    float hr2 = 0.f, hi2 = 0.f, hr3 = 0.f, hi3 = 0.f;

    const int bL = b * L;
    const int flat4 = flat >> 2;

    #pragma unroll
    for (int l = 0; l < L; ++l) {
        const int uoff4 = (bL + l) * (RCHW >> 2) + flat4;  // float4 index
        const float4 vr = __ldcs(&ur[uoff4]);   // read-once: evict-first
        const float4 vi = __ldcs(&ui[uoff4]);

        const int aoff = (bL + l) * RCW;
        const float2 A0 = g_A[aoff + aidx0];
        const float2 A1 = g_A[aoff + aidx1];
        const float2 A2 = g_A[aoff + aidx2];
        const float2 A3 = g_A[aoff + aidx3];

        float nr, ni;
        nr = A0.x * hr0 - A0.y * hi0 + vr.x;
        ni = A0.x * hi0 + A0.y * hr0 + vi.x;
        hr0 = nr; hi0 = ni;

        nr = A1.x * hr1 - A1.y * hi1 + vr.y;
        ni = A1.x * hi1 + A1.y * hr1 + vi.y;
        hr1 = nr; hi1 = ni;

        nr = A2.x * hr2 - A2.y * hi2 + vr.z;
        ni = A2.x * hi2 + A2.y * hr2 + vi.z;
        hr2 = nr; hi2 = ni;

        nr = A3.x * hr3 - A3.y * hi3 + vr.w;
        ni = A3.x * hi3 + A3.y * hr3 + vi.w;
        hr3 = nr; hi3 = ni;

        __stcs(&out[uoff4],             make_float4(hr0, hr1, hr2, hr3)); // real half
        __stcs(&out[(NU >> 2) + uoff4], make_float4(hi0, hi1, hi2, hi3)); // imag half
    }
}

// ---------------------------------------------------------------------------
// kernel_launch: two launches, graph-capturable, no allocations.
// Inputs (metadata order): nu_rate, theta_rate, dt_seq, u_real, u_imag.
// Output: float32, shape (2, B, L, R, C, H, Wf) = 57,802,752 elements.
// ---------------------------------------------------------------------------
extern "C" void kernel_launch(void* const* d_in, const int* in_sizes, int n_in,
                              void* d_out, int out_size) {
    const float*  nu = (const float*)d_in[0];
    const float*  th = (const float*)d_in[1];
    const float*  dt = (const float*)d_in[2];
    const float4* ur = (const float4*)d_in[3];
    const float4* ui = (const float4*)d_in[4];
    float4* out = (float4*)d_out;

    compute_A_kernel<<<(NA + 255) / 256, 256>>>(nu, th, dt);

    constexpr int nthreads = (B * RCHW) / 4;   // 301,056
    scan_kernel<<<nthreads / 256, 256>>>(ur, ui, out);
}